// round 5
// baseline (speedup 1.0000x reference)
#include <cuda_runtime.h>

#define HH   512
#define WW   512
#define BB   4
#define CINC 55
#define NRr  30
#define NCc  20
#define NCELL 600
#define OUTX 57671680   // 4*55*512*512

typedef unsigned long long u64;

// Scratch (device globals; no allocation)
__device__ float g_Stop[NCELL];
__device__ float g_Sbot[NCELL];
__device__ float g_topm[NCELL];
__device__ float g_sig[NCELL];
__device__ float g_wtsum[18];
__device__ float g_btsum;
// duplicated weight pairs: [c][d][o][k], each entry = (w, w) packed in 64 bits
__device__ u64  g_wpack[CINC * 450];

__device__ __forceinline__ u64 ffma2(u64 a, u64 b, u64 c) {
    u64 d;
    asm("fma.rn.f32x2 %0, %1, %2, %3;" : "=l"(d) : "l"(a), "l"(b), "l"(c));
    return d;
}
__device__ __forceinline__ float2 unpack2(u64 v) {
    float2 f;
    asm("mov.b64 {%0, %1}, %2;" : "=f"(f.x), "=f"(f.y) : "l"(v));
    return f;
}

// ---------------------------------------------------------------------------
// Kernel 1: zero accumulators, fold top head (36ch -> channel-sum 18-vector),
// and pre-pack duplicated conv-weight pairs into g_wpack.
// ---------------------------------------------------------------------------
__global__ __launch_bounds__(640) void prep_kernel(
    const float* __restrict__ w1, const float* __restrict__ w2,
    const float* __restrict__ w3,
    const float* __restrict__ wt, const float* __restrict__ bt)
{
    int t = blockIdx.x * blockDim.x + threadIdx.x;
    const int total = 3 * 6 * CINC * 25;   // 24750
    if (t < total) {
        int d  = t / (6 * CINC * 25);
        int r  = t - d * (6 * CINC * 25);
        int o  = r / (CINC * 25);
        int r2 = r - o * (CINC * 25);
        int c  = r2 / 25;
        int k  = r2 - c * 25;
        const float* w = (d == 0) ? w1 : (d == 1 ? w2 : w3);
        unsigned bits = __float_as_uint(w[(o * CINC + c) * 25 + k]);
        g_wpack[c * 450 + d * 150 + o * 25 + k] = ((u64)bits << 32) | (u64)bits;
    }
    if (blockIdx.x == 0) {
        int s = threadIdx.x;
        if (s < NCELL) { g_Stop[s] = 0.f; g_Sbot[s] = 0.f; }
        if (s < 18) {
            float a = 0.f;
            #pragma unroll 4
            for (int c = 0; c < 36; c++) a += wt[c * 18 + s];
            g_wtsum[s] = a;
        }
        if (s == 18) {
            float a = 0.f;
            for (int c = 0; c < 36; c++) a += bt[c];
            g_btsum = a;
        }
    }
}

// ---------------------------------------------------------------------------
// Kernel 2: fused 3x dilated 5x5 conv (55->18) + ReLU + feat store +
//           per-cell head accumulation. FFMA2 (f32x2) x-pair packing.
// Tile: 32x32 outputs, 256 threads (16 x-pairs x 16 rows), 2 rows/thread.
// Weights: pre-duplicated u64 pairs staged in SMEM -> LDS.64 broadcast.
// Two tile copies (tB shifted one float) keep every s-load an aligned LDS.64.
// ---------------------------------------------------------------------------
__global__ __launch_bounds__(256, 1) void conv_kernel(
    const float* __restrict__ x,
    const int*   __restrict__ row_seg,
    const int*   __restrict__ col_seg,
    const float* __restrict__ b1, const float* __restrict__ b2,
    const float* __restrict__ b3,
    const float* __restrict__ wbv, const float* __restrict__ bbv,
    float* __restrict__ out)
{
    __shared__ __align__(16) float tA[44 * 44];
    __shared__ __align__(16) float tB[44 * 44];   // tB[j] = tA[j+1] per row
    __shared__ __align__(16) u64  sw[450];        // duplicated weight pairs
    __shared__ float sbias[18], swt[18], swb[18];
    __shared__ float sbt, sbb;
    __shared__ float cT[NCELL], cB[NCELL];

    const int tid = threadIdx.x;
    const int tx  = tid & 15;      // x-pair index (0..15)
    const int ty  = tid >> 4;      // row index (0..15)
    const int gx0 = blockIdx.x * 32;
    const int gy0 = blockIdx.y * 32;
    const int b   = blockIdx.z;

    for (int t = tid; t < NCELL; t += 256) { cT[t] = 0.f; cB[t] = 0.f; }
    if (tid < 6) {
        sbias[tid]      = b1[tid];
        sbias[6 + tid]  = b2[tid];
        sbias[12 + tid] = b3[tid];
    }
    if (tid < 18) { swt[tid] = g_wtsum[tid]; swb[tid] = wbv[tid]; }
    if (tid == 0) { sbt = g_btsum; sbb = bbv[0]; }

    u64 acc[2][18];
    #pragma unroll
    for (int p = 0; p < 2; p++)
        #pragma unroll
        for (int j = 0; j < 18; j++) acc[p][j] = 0ull;

    for (int c = 0; c < CINC; c++) {
        // stage weight pairs for this channel
        const u64* wp = g_wpack + c * 450;
        for (int t = tid; t < 450; t += 256) sw[t] = wp[t];
        // stage input tile + shifted copy (zero-pad outside image)
        const float* xc = x + (((size_t)(b * CINC + c)) << 18);
        for (int t = tid; t < 44 * 44; t += 256) {
            int rr = t / 44, cc = t - rr * 44;
            int gy = gy0 - 6 + rr;
            int gx = gx0 - 6 + cc;
            float v = 0.f;
            if ((unsigned)gy < 512u && (unsigned)gx < 512u)
                v = xc[(gy << 9) + gx];
            tA[t] = v;
            if (cc > 0) tB[t - 1] = v;
        }
        __syncthreads();

        #pragma unroll
        for (int ky = 0; ky < 5; ky++) {
            #pragma unroll
            for (int kx = 0; kx < 5; kx++) {
                const int k = ky * 5 + kx;
                u64 w[18];
                #pragma unroll
                for (int o = 0; o < 6; o++) {
                    w[o]      = sw[       o * 25 + k];
                    w[6 + o]  = sw[150 + o * 25 + k];
                    w[12 + o] = sw[300 + o * 25 + k];
                }
                #pragma unroll
                for (int p = 0; p < 2; p++) {
                    const int yb = ty + 16 * p + 6;
                    const int xb = 2 * tx + 6;
                    // dilation 1 (odd col offset -> shifted copy tB)
                    {
                        const int r  = yb + (ky - 2);
                        const int cx = xb + (kx - 2);
                        u64 s = ((kx - 2) & 1)
                              ? *(const u64*)&tB[r * 44 + cx - 1]
                              : *(const u64*)&tA[r * 44 + cx];
                        #pragma unroll
                        for (int o = 0; o < 6; o++)
                            acc[p][o] = ffma2(s, w[o], acc[p][o]);
                    }
                    // dilation 2 (always even -> tA)
                    {
                        const int r  = yb + 2 * (ky - 2);
                        const int cx = xb + 2 * (kx - 2);
                        u64 s = *(const u64*)&tA[r * 44 + cx];
                        #pragma unroll
                        for (int o = 0; o < 6; o++)
                            acc[p][6 + o] = ffma2(s, w[6 + o], acc[p][6 + o]);
                    }
                    // dilation 3
                    {
                        const int r  = yb + 3 * (ky - 2);
                        const int cx = xb + 3 * (kx - 2);
                        u64 s = ((3 * (kx - 2)) & 1)
                              ? *(const u64*)&tB[r * 44 + cx - 1]
                              : *(const u64*)&tA[r * 44 + cx];
                        #pragma unroll
                        for (int o = 0; o < 6; o++)
                            acc[p][12 + o] = ffma2(s, w[12 + o], acc[p][12 + o]);
                    }
                }
            }
        }
        __syncthreads();
    }

    // epilogue: bias+relu, float2 feat stores (channels 36..53), cell accum
    const int gx  = gx0 + 2 * tx;
    const int cs0 = col_seg[gx];
    const int cs1 = col_seg[gx + 1];
    #pragma unroll
    for (int p = 0; p < 2; p++) {
        const int gy    = gy0 + ty + 16 * p;
        const int cellb = row_seg[gy] * NCc;
        float st0 = sbt, st1 = sbt, sb0 = sbb, sb1 = sbb;
        const unsigned pix = ((unsigned)gy << 9) + (unsigned)gx;
        #pragma unroll
        for (int j = 0; j < 18; j++) {
            float2 v = unpack2(acc[p][j]);
            float f0 = fmaxf(v.x + sbias[j], 0.f);
            float f1 = fmaxf(v.y + sbias[j], 0.f);
            *(float2*)&out[(((unsigned)(b * CINC + 36 + j)) << 18) + pix] =
                make_float2(f0, f1);
            st0 = fmaf(swt[j], f0, st0);
            st1 = fmaf(swt[j], f1, st1);
            sb0 = fmaf(swb[j], f0, sb0);
            sb1 = fmaf(swb[j], f1, sb1);
        }
        atomicAdd(&cT[cellb + cs0], st0);
        atomicAdd(&cT[cellb + cs1], st1);
        atomicAdd(&cB[cellb + cs0], sb0);
        atomicAdd(&cB[cellb + cs1], sb1);
    }
    __syncthreads();
    for (int t = tid; t < NCELL; t += 256) {
        float v0 = cT[t], v1 = cB[t];
        if (v0 != 0.f) atomicAdd(&g_Stop[t], v0);
        if (v1 != 0.f) atomicAdd(&g_Sbot[t], v1);
    }
}

// ---------------------------------------------------------------------------
// Kernel 3: finalize means -> top_m, sigmoid(bot_m); write pools output.
// ---------------------------------------------------------------------------
__global__ __launch_bounds__(640) void finalize_kernel(
    const int* __restrict__ row_seg, const int* __restrict__ col_seg,
    float* __restrict__ out)
{
    __shared__ int rc[NRr];
    __shared__ int cc[NCc];
    int t = threadIdx.x;
    if (t < NRr) rc[t] = 0;
    if (t < NCc) cc[t] = 0;
    __syncthreads();
    if (t < 512) {
        atomicAdd(&rc[row_seg[t]], 1);
        atomicAdd(&cc[col_seg[t]], 1);
    }
    __syncthreads();
    if (t < NCELL) {
        int r = t / NCc, c = t - r * NCc;
        float pix = (float)(rc[r] * cc[c]);
        float tm = g_Stop[t] / (pix * (float)(BB * 36));
        float bm = g_Sbot[t] / (pix * (float)BB);
        g_topm[t] = tm;
        float sg = 1.f / (1.f + expf(-bm));
        g_sig[t] = sg;
        #pragma unroll
        for (int b = 0; b < BB; b++)
            out[OUTX + b * NCELL + t] = sg;
    }
}

// ---------------------------------------------------------------------------
// Kernel 4: broadcast fill of channels 0..35 (top_m) and 54 (sigmoid(bot_m)).
// ---------------------------------------------------------------------------
__global__ __launch_bounds__(256) void bcast_kernel(
    const int* __restrict__ row_seg, const int* __restrict__ col_seg,
    float* __restrict__ out)
{
    unsigned i  = blockIdx.x * 256u + threadIdx.x;   // over B*H*W/4
    unsigned x4 = (i & 127u) << 2;
    unsigned y  = (i >> 7) & 511u;
    unsigned b  = i >> 16;
    int rb = __ldg(&row_seg[y]) * NCc;
    int c0 = __ldg(&col_seg[x4]);
    int c1 = __ldg(&col_seg[x4 + 1]);
    int c2 = __ldg(&col_seg[x4 + 2]);
    int c3 = __ldg(&col_seg[x4 + 3]);
    float4 tv = make_float4(g_topm[rb + c0], g_topm[rb + c1],
                            g_topm[rb + c2], g_topm[rb + c3]);
    float4 sv = make_float4(g_sig[rb + c0], g_sig[rb + c1],
                            g_sig[rb + c2], g_sig[rb + c3]);
    unsigned base = ((b * (unsigned)CINC) << 18) + (y << 9) + x4;
    #pragma unroll
    for (int ch = 0; ch < 36; ch++)
        *(float4*)&out[base + ((unsigned)ch << 18)] = tv;
    *(float4*)&out[base + (54u << 18)] = sv;
}

// ---------------------------------------------------------------------------
extern "C" void kernel_launch(void* const* d_in, const int* in_sizes, int n_in,
                              void* d_out, int out_size) {
    const float* x       = (const float*)d_in[0];
    const int*   row_seg = (const int*)d_in[1];
    const int*   col_seg = (const int*)d_in[2];
    const float* w1 = (const float*)d_in[3];
    const float* b1 = (const float*)d_in[4];
    const float* w2 = (const float*)d_in[5];
    const float* b2 = (const float*)d_in[6];
    const float* w3 = (const float*)d_in[7];
    const float* b3 = (const float*)d_in[8];
    const float* wt = (const float*)d_in[9];
    const float* bt = (const float*)d_in[10];
    const float* wb = (const float*)d_in[11];
    const float* bb = (const float*)d_in[12];
    float* out = (float*)d_out;

    prep_kernel<<<39, 640>>>(w1, w2, w3, wt, bt);

    dim3 grid(WW / 32, HH / 32, BB);
    conv_kernel<<<grid, 256>>>(x, row_seg, col_seg,
                               b1, b2, b3, wb, bb, out);

    finalize_kernel<<<1, 640>>>(row_seg, col_seg, out);

    bcast_kernel<<<(BB * HH * WW / 4) / 256, 256>>>(row_seg, col_seg, out);
}

// round 6
// speedup vs baseline: 1.0846x; 1.0846x over previous
#include <cuda_runtime.h>

#define HH   512
#define WW   512
#define BB   4
#define CINC 55
#define NRr  30
#define NCc  20
#define NCELL 600
#define OUTX 57671680   // 4*55*512*512

typedef unsigned long long u64;

// Scratch (device globals; no allocation)
__device__ float g_Stop[NCELL];
__device__ float g_Sbot[NCELL];
__device__ float g_topm[NCELL];
__device__ float g_sig[NCELL];
__device__ float g_wtsum[18];

// One dilation's conv weights [o][c][k] (6*55*25 floats = 33 KB), swapped
// between passes via async D2D memcpy-to-symbol (a graph memcpy node).
__constant__ float cw[6 * CINC * 25];

__device__ __forceinline__ u64 ffma2(u64 a, u64 b, u64 c) {
    u64 d;
    asm("fma.rn.f32x2 %0, %1, %2, %3;" : "=l"(d) : "l"(a), "l"(b), "l"(c));
    return d;
}
__device__ __forceinline__ float2 unpack2(u64 v) {
    float2 f;
    asm("mov.b64 {%0, %1}, %2;" : "=f"(f.x), "=f"(f.y) : "l"(v));
    return f;
}
__device__ __forceinline__ u64 dup2(float w) {
    u64 r;
    asm("mov.b64 %0, {%1, %1};" : "=l"(r) : "f"(w));
    return r;
}

// ---------------------------------------------------------------------------
// Kernel 1: zero cell accumulators; fold top head into channel-sum 18-vector.
// ---------------------------------------------------------------------------
__global__ __launch_bounds__(640) void prep_kernel(const float* __restrict__ wt) {
    int t = threadIdx.x;
    if (t < NCELL) { g_Stop[t] = 0.f; g_Sbot[t] = 0.f; }
    if (t < 18) {
        float s = 0.f;
        #pragma unroll 4
        for (int c = 0; c < 36; c++) s += wt[c * 18 + t];
        g_wtsum[t] = s;
    }
}

// ---------------------------------------------------------------------------
// Kernel 2 (x3): one dilation's 5x5 conv (55->6) + ReLU + feat store +
// per-cell head accumulation. FFMA2 x-pair packing; weights from __constant__
// (LDC port — zero crossbar); input pairs via aligned LDS.64 (tB = tA shifted
// one float handles odd-dilation column offsets).
// Tile: 32 rows x 64 cols, 128 threads (16 pair-cols x 8 rows), 8 pairs/thread.
// ---------------------------------------------------------------------------
template <int D>
__global__ __launch_bounds__(128, 3) void pass_kernel(
    const float* __restrict__ x,
    const int*   __restrict__ row_seg,
    const int*   __restrict__ col_seg,
    const float* __restrict__ bias,   // this dilation's 6 biases
    const float* __restrict__ wbv,    // wb + 6*(D-1)
    float* __restrict__ out)
{
    constexpr int PAD = 2 * D;
    constexpr int SW  = 64 + 4 * D;
    constexpr int SH  = 32 + 4 * D;
    constexpr int OCB = 36 + 6 * (D - 1);   // output channel base in out_x

    __shared__ __align__(16) float tA[SH * SW];
    __shared__ __align__(16) float tB[(D == 2) ? 8 : (SH * SW)];
    __shared__ float cT[NCELL], cB[NCELL];
    __shared__ float sb6[6], st6[6], sw6[6];

    const int tid = threadIdx.x;
    const int tx  = tid & 15;     // pair-col (0..15)
    const int ty  = tid >> 4;     // row (0..7)
    const int gx0 = blockIdx.x * 64;
    const int gy0 = blockIdx.y * 32;
    const int b   = blockIdx.z;

    for (int t = tid; t < NCELL; t += 128) { cT[t] = 0.f; cB[t] = 0.f; }
    if (tid < 6) {
        sb6[tid] = bias[tid];
        st6[tid] = g_wtsum[6 * (D - 1) + tid];
        sw6[tid] = wbv[tid];
    }

    u64 acc[4][2][6];
    #pragma unroll
    for (int r = 0; r < 4; r++)
        #pragma unroll
        for (int q = 0; q < 2; q++)
            #pragma unroll
            for (int o = 0; o < 6; o++) acc[r][q][o] = 0ull;

    for (int c = 0; c < CINC; c++) {
        const float* xc = x + (((size_t)(b * CINC + c)) << 18);
        for (int t = tid; t < SH * SW; t += 128) {
            int rr = t / SW, cc = t - rr * SW;
            int gy = gy0 - PAD + rr;
            int gx = gx0 - PAD + cc;
            float v = 0.f;
            if ((unsigned)gy < 512u && (unsigned)gx < 512u)
                v = xc[(gy << 9) + gx];
            tA[t] = v;
            if (D != 2 && cc > 0) tB[t - 1] = v;
        }
        __syncthreads();

        #pragma unroll
        for (int ky = 0; ky < 5; ky++) {
            #pragma unroll
            for (int kx = 0; kx < 5; kx++) {
                const int kk = ky * 5 + kx;
                u64 wp[6];
                #pragma unroll
                for (int o = 0; o < 6; o++)
                    wp[o] = dup2(cw[(o * CINC + c) * 25 + kk]);
                const int dy = (ky - 2) * D;
                const int dx = (kx - 2) * D;
                #pragma unroll
                for (int r = 0; r < 4; r++) {
                    const int row = ty + 8 * r + PAD + dy;
                    #pragma unroll
                    for (int q = 0; q < 2; q++) {
                        const int col = 2 * (tx + 16 * q) + PAD + dx;
                        u64 s;
                        if (D != 2 && (dx & 1))
                            s = *(const u64*)&tB[row * SW + col - 1];
                        else
                            s = *(const u64*)&tA[row * SW + col];
                        #pragma unroll
                        for (int o = 0; o < 6; o++)
                            acc[r][q][o] = ffma2(s, wp[o], acc[r][q][o]);
                    }
                }
            }
        }
        __syncthreads();
    }

    // epilogue: bias + relu, float2 feat stores, partial cell sums
    #pragma unroll
    for (int r = 0; r < 4; r++) {
        const int gy    = gy0 + ty + 8 * r;
        const int cellb = row_seg[gy] * NCc;
        #pragma unroll
        for (int q = 0; q < 2; q++) {
            const int gxp = gx0 + 2 * (tx + 16 * q);
            const int cs0 = col_seg[gxp];
            const int cs1 = col_seg[gxp + 1];
            float st0 = 0.f, st1 = 0.f, sb0 = 0.f, sb1 = 0.f;
            const unsigned pix = ((unsigned)gy << 9) + (unsigned)gxp;
            #pragma unroll
            for (int o = 0; o < 6; o++) {
                float2 v = unpack2(acc[r][q][o]);
                float f0 = fmaxf(v.x + sb6[o], 0.f);
                float f1 = fmaxf(v.y + sb6[o], 0.f);
                *(float2*)&out[(((unsigned)(b * CINC + OCB + o)) << 18) + pix] =
                    make_float2(f0, f1);
                st0 = fmaf(st6[o], f0, st0);
                st1 = fmaf(st6[o], f1, st1);
                sb0 = fmaf(sw6[o], f0, sb0);
                sb1 = fmaf(sw6[o], f1, sb1);
            }
            atomicAdd(&cT[cellb + cs0], st0);
            atomicAdd(&cT[cellb + cs1], st1);
            atomicAdd(&cB[cellb + cs0], sb0);
            atomicAdd(&cB[cellb + cs1], sb1);
        }
    }
    __syncthreads();
    for (int t = tid; t < NCELL; t += 128) {
        float v0 = cT[t], v1 = cB[t];
        if (v0 != 0.f) atomicAdd(&g_Stop[t], v0);
        if (v1 != 0.f) atomicAdd(&g_Sbot[t], v1);
    }
}

// ---------------------------------------------------------------------------
// Kernel 3: finalize means (adding head-bias terms) -> top_m, sigmoid(bot_m);
// write pools output.
// ---------------------------------------------------------------------------
__global__ __launch_bounds__(640) void finalize_kernel(
    const int* __restrict__ row_seg, const int* __restrict__ col_seg,
    const float* __restrict__ bt, const float* __restrict__ bb,
    float* __restrict__ out)
{
    __shared__ int rc[NRr];
    __shared__ int cc[NCc];
    int t = threadIdx.x;
    if (t < NRr) rc[t] = 0;
    if (t < NCc) cc[t] = 0;
    __syncthreads();
    if (t < 512) {
        atomicAdd(&rc[row_seg[t]], 1);
        atomicAdd(&cc[col_seg[t]], 1);
    }
    __syncthreads();
    if (t < NCELL) {
        float btsum = 0.f;
        for (int c = 0; c < 36; c++) btsum += bt[c];
        float bb0 = bb[0];
        int r = t / NCc, c = t - r * NCc;
        float pix = (float)(rc[r] * cc[c]);
        float tm = (g_Stop[t] + (float)BB * pix * btsum) / (pix * (float)(BB * 36));
        float bm = (g_Sbot[t] + (float)BB * pix * bb0) / (pix * (float)BB);
        g_topm[t] = tm;
        float sg = 1.f / (1.f + expf(-bm));
        g_sig[t] = sg;
        #pragma unroll
        for (int b = 0; b < BB; b++)
            out[OUTX + b * NCELL + t] = sg;
    }
}

// ---------------------------------------------------------------------------
// Kernel 4: broadcast fill of channels 0..35 (top_m) and 54 (sigmoid(bot_m)).
// ---------------------------------------------------------------------------
__global__ __launch_bounds__(256) void bcast_kernel(
    const int* __restrict__ row_seg, const int* __restrict__ col_seg,
    float* __restrict__ out)
{
    unsigned i  = blockIdx.x * 256u + threadIdx.x;   // over B*H*W/4
    unsigned x4 = (i & 127u) << 2;
    unsigned y  = (i >> 7) & 511u;
    unsigned b  = i >> 16;
    int rb = __ldg(&row_seg[y]) * NCc;
    int c0 = __ldg(&col_seg[x4]);
    int c1 = __ldg(&col_seg[x4 + 1]);
    int c2 = __ldg(&col_seg[x4 + 2]);
    int c3 = __ldg(&col_seg[x4 + 3]);
    float4 tv = make_float4(g_topm[rb + c0], g_topm[rb + c1],
                            g_topm[rb + c2], g_topm[rb + c3]);
    float4 sv = make_float4(g_sig[rb + c0], g_sig[rb + c1],
                            g_sig[rb + c2], g_sig[rb + c3]);
    unsigned base = ((b * (unsigned)CINC) << 18) + (y << 9) + x4;
    #pragma unroll
    for (int ch = 0; ch < 36; ch++)
        *(float4*)&out[base + ((unsigned)ch << 18)] = tv;
    *(float4*)&out[base + (54u << 18)] = sv;
}

// ---------------------------------------------------------------------------
extern "C" void kernel_launch(void* const* d_in, const int* in_sizes, int n_in,
                              void* d_out, int out_size) {
    const float* x       = (const float*)d_in[0];
    const int*   row_seg = (const int*)d_in[1];
    const int*   col_seg = (const int*)d_in[2];
    const float* w1 = (const float*)d_in[3];
    const float* b1 = (const float*)d_in[4];
    const float* w2 = (const float*)d_in[5];
    const float* b2 = (const float*)d_in[6];
    const float* w3 = (const float*)d_in[7];
    const float* b3 = (const float*)d_in[8];
    const float* wt = (const float*)d_in[9];
    const float* bt = (const float*)d_in[10];
    const float* wb = (const float*)d_in[11];
    const float* bb = (const float*)d_in[12];
    float* out = (float*)d_out;

    const size_t WBYTES = 6 * CINC * 25 * sizeof(float);   // 33000

    prep_kernel<<<1, 640>>>(wt);

    dim3 grid(WW / 64, HH / 32, BB);

    cudaMemcpyToSymbolAsync(cw, w1, WBYTES, 0, cudaMemcpyDeviceToDevice, 0);
    pass_kernel<1><<<grid, 128>>>(x, row_seg, col_seg, b1, wb + 0, out);

    cudaMemcpyToSymbolAsync(cw, w2, WBYTES, 0, cudaMemcpyDeviceToDevice, 0);
    pass_kernel<2><<<grid, 128>>>(x, row_seg, col_seg, b2, wb + 6, out);

    cudaMemcpyToSymbolAsync(cw, w3, WBYTES, 0, cudaMemcpyDeviceToDevice, 0);
    pass_kernel<3><<<grid, 128>>>(x, row_seg, col_seg, b3, wb + 12, out);

    finalize_kernel<<<1, 640>>>(row_seg, col_seg, bt, bb, out);

    bcast_kernel<<<(BB * HH * WW / 4) / 256, 256>>>(row_seg, col_seg, out);
}

// round 10
// speedup vs baseline: 1.2146x; 1.1198x over previous
#include <cuda_runtime.h>

#define HH   512
#define WW   512
#define BB   4
#define CINC 55
#define NRr  30
#define NCc  20
#define NCELL 600
#define OUTX 57671680   // 4*55*512*512

typedef unsigned long long u64;

// Scratch (device globals; no allocation)
__device__ float g_Stop[NCELL];
__device__ float g_Sbot[NCELL];
__device__ float g_topm[NCELL];
__device__ float g_sig[NCELL];
__device__ float g_wtsum[18];
// duplicated weight pairs: [c][d][o][k], entry = (w,w) packed in 64 bits
__device__ u64  g_wpack[CINC * 450];

__device__ __forceinline__ u64 ffma2(u64 a, u64 b, u64 c) {
    u64 d;
    asm("fma.rn.f32x2 %0, %1, %2, %3;" : "=l"(d) : "l"(a), "l"(b), "l"(c));
    return d;
}
__device__ __forceinline__ float2 unpack2(u64 v) {
    float2 f;
    asm("mov.b64 {%0, %1}, %2;" : "=f"(f.x), "=f"(f.y) : "l"(v));
    return f;
}

// ---------------------------------------------------------------------------
// Kernel 1: zero accumulators, fold top head (36ch -> channel-sum 18-vector),
// pre-pack duplicated conv-weight pairs into g_wpack.
// ---------------------------------------------------------------------------
__global__ __launch_bounds__(640) void prep_kernel(
    const float* __restrict__ w1, const float* __restrict__ w2,
    const float* __restrict__ w3, const float* __restrict__ wt)
{
    int t = blockIdx.x * blockDim.x + threadIdx.x;
    const int total = 3 * 6 * CINC * 25;   // 24750
    if (t < total) {
        int d  = t / (6 * CINC * 25);
        int r  = t - d * (6 * CINC * 25);
        int o  = r / (CINC * 25);
        int r2 = r - o * (CINC * 25);
        int c  = r2 / 25;
        int k  = r2 - c * 25;
        const float* w = (d == 0) ? w1 : (d == 1 ? w2 : w3);
        unsigned bits = __float_as_uint(w[(o * CINC + c) * 25 + k]);
        g_wpack[c * 450 + d * 150 + o * 25 + k] = ((u64)bits << 32) | (u64)bits;
    }
    if (blockIdx.x == 0) {
        int s = threadIdx.x;
        if (s < NCELL) { g_Stop[s] = 0.f; g_Sbot[s] = 0.f; }
        if (s < 18) {
            float a = 0.f;
            #pragma unroll 4
            for (int c = 0; c < 36; c++) a += wt[c * 18 + s];
            g_wtsum[s] = a;
        }
    }
}

// ---------------------------------------------------------------------------
// Kernel 2: ALL dilations in one launch (z = b*3 + d). Per block: one
// dilation's 5x5 conv (55->6) + ReLU + feat store + per-cell head accum.
// FFMA2 x-pair packing, Npx=6 pairs/thread (FMA-bound balance point).
// Tile 48x32 (last x-tile partial, guarded). 128 thr = 8 pair-cols x 16 rows;
// q in {0,1,2} col-groups, r in {0,1} row-groups.
// Weights: u64 pairs via __ldg (off-crossbar). tB = tA shifted one float for
// odd column offsets (D=1,3).
// ---------------------------------------------------------------------------
#define MAXSH 44   // 32 + 4*3
#define MAXSW 60   // 48 + 4*3

template <int D>
__device__ __forceinline__ void conv_body(
    const float* __restrict__ x,
    const int*   __restrict__ row_seg,
    const int*   __restrict__ col_seg,
    const float* __restrict__ bias6,
    const float* __restrict__ wb6,
    float* __restrict__ out,
    float* tA, float* tB, float* cT, float* cB,
    int b, int gx0, int gy0)
{
    constexpr int PAD = 2 * D;
    constexpr int SW  = 48 + 4 * D;
    constexpr int SH  = 32 + 4 * D;
    constexpr int OCB = 36 + 6 * (D - 1);

    const int tid = threadIdx.x;
    const int tx  = tid & 7;     // pair-col within group (0..7)
    const int ty  = tid >> 3;    // row (0..15)

    __shared__ float sb6[6], st6[6], sw6[6];
    if (tid < 6) {
        sb6[tid] = bias6[tid];
        st6[tid] = g_wtsum[6 * (D - 1) + tid];
        sw6[tid] = wb6[tid];
    }
    for (int t = tid; t < NCELL; t += 128) { cT[t] = 0.f; cB[t] = 0.f; }

    u64 acc[2][3][6];
    #pragma unroll
    for (int r = 0; r < 2; r++)
        #pragma unroll
        for (int q = 0; q < 3; q++)
            #pragma unroll
            for (int o = 0; o < 6; o++) acc[r][q][o] = 0ull;

    for (int c = 0; c < CINC; c++) {
        const float* xc = x + (((size_t)(b * CINC + c)) << 18);
        for (int t = tid; t < SH * SW; t += 128) {
            int rr = t / SW, cc = t - rr * SW;
            int gy = gy0 - PAD + rr;
            int gx = gx0 - PAD + cc;
            float v = 0.f;
            if ((unsigned)gy < 512u && (unsigned)gx < 512u)
                v = xc[(gy << 9) + gx];
            tA[t] = v;
            if (D != 2 && cc > 0) tB[t - 1] = v;
        }
        __syncthreads();

        const u64* wc = g_wpack + c * 450 + (D - 1) * 150;
        #pragma unroll
        for (int ky = 0; ky < 5; ky++) {
            #pragma unroll
            for (int kx = 0; kx < 5; kx++) {
                const int kk = ky * 5 + kx;
                u64 w[6];
                #pragma unroll
                for (int o = 0; o < 6; o++)
                    w[o] = __ldg(wc + o * 25 + kk);
                const int dy = (ky - 2) * D;
                const int dx = (kx - 2) * D;
                #pragma unroll
                for (int r = 0; r < 2; r++) {
                    const int row = ty + 16 * r + PAD + dy;
                    #pragma unroll
                    for (int q = 0; q < 3; q++) {
                        const int col = 2 * (8 * q + tx) + PAD + dx;
                        u64 s;
                        if (D != 2 && (dx & 1))
                            s = *(const u64*)&tB[row * SW + col - 1];
                        else
                            s = *(const u64*)&tA[row * SW + col];
                        #pragma unroll
                        for (int o = 0; o < 6; o++)
                            acc[r][q][o] = ffma2(s, w[o], acc[r][q][o]);
                    }
                }
            }
        }
        __syncthreads();
    }

    // epilogue: bias+relu, float2 feat stores, partial cell sums (guarded)
    #pragma unroll
    for (int r = 0; r < 2; r++) {
        const int gy    = gy0 + ty + 16 * r;
        const int cellb = row_seg[gy] * NCc;
        #pragma unroll
        for (int q = 0; q < 3; q++) {
            const int gxp = gx0 + 2 * (8 * q + tx);
            if (gxp >= 512) continue;
            const int cs0 = col_seg[gxp];
            const int cs1 = col_seg[gxp + 1];
            float st0 = 0.f, st1 = 0.f, sb0 = 0.f, sb1 = 0.f;
            const unsigned pix = ((unsigned)gy << 9) + (unsigned)gxp;
            #pragma unroll
            for (int o = 0; o < 6; o++) {
                float2 v = unpack2(acc[r][q][o]);
                float f0 = fmaxf(v.x + sb6[o], 0.f);
                float f1 = fmaxf(v.y + sb6[o], 0.f);
                *(float2*)&out[(((unsigned)(b * CINC + OCB + o)) << 18) + pix] =
                    make_float2(f0, f1);
                st0 = fmaf(st6[o], f0, st0);
                st1 = fmaf(st6[o], f1, st1);
                sb0 = fmaf(sw6[o], f0, sb0);
                sb1 = fmaf(sw6[o], f1, sb1);
            }
            atomicAdd(&cT[cellb + cs0], st0);
            atomicAdd(&cT[cellb + cs1], st1);
            atomicAdd(&cB[cellb + cs0], sb0);
            atomicAdd(&cB[cellb + cs1], sb1);
        }
    }
    __syncthreads();
    for (int t = tid; t < NCELL; t += 128) {
        float v0 = cT[t], v1 = cB[t];
        if (v0 != 0.f) atomicAdd(&g_Stop[t], v0);
        if (v1 != 0.f) atomicAdd(&g_Sbot[t], v1);
    }
}

__global__ __launch_bounds__(128, 4) void conv_kernel(
    const float* __restrict__ x,
    const int*   __restrict__ row_seg,
    const int*   __restrict__ col_seg,
    const float* __restrict__ b1, const float* __restrict__ b2,
    const float* __restrict__ b3,
    const float* __restrict__ wbv,
    float* __restrict__ out)
{
    __shared__ __align__(16) float tA[MAXSH * MAXSW];
    __shared__ __align__(16) float tB[MAXSH * MAXSW];
    __shared__ float cT[NCELL], cB[NCELL];

    const int bz  = blockIdx.z;
    const int b   = bz / 3;
    const int d   = bz - b * 3;
    const int gx0 = blockIdx.x * 48;
    const int gy0 = blockIdx.y * 32;

    if (d == 0)
        conv_body<1>(x, row_seg, col_seg, b1, wbv + 0,  out, tA, tB, cT, cB, b, gx0, gy0);
    else if (d == 1)
        conv_body<2>(x, row_seg, col_seg, b2, wbv + 6,  out, tA, tB, cT, cB, b, gx0, gy0);
    else
        conv_body<3>(x, row_seg, col_seg, b3, wbv + 12, out, tA, tB, cT, cB, b, gx0, gy0);
}

// ---------------------------------------------------------------------------
// Kernel 3: finalize means (adding head biases) -> top_m, sigmoid(bot_m);
// write pools output.
// ---------------------------------------------------------------------------
__global__ __launch_bounds__(640) void finalize_kernel(
    const int* __restrict__ row_seg, const int* __restrict__ col_seg,
    const float* __restrict__ bt, const float* __restrict__ bb,
    float* __restrict__ out)
{
    __shared__ int rc[NRr];
    __shared__ int cc[NCc];
    int t = threadIdx.x;
    if (t < NRr) rc[t] = 0;
    if (t < NCc) cc[t] = 0;
    __syncthreads();
    if (t < 512) {
        atomicAdd(&rc[row_seg[t]], 1);
        atomicAdd(&cc[col_seg[t]], 1);
    }
    __syncthreads();
    if (t < NCELL) {
        float btsum = 0.f;
        for (int c = 0; c < 36; c++) btsum += bt[c];
        float bb0 = bb[0];
        int r = t / NCc, c = t - r * NCc;
        float pix = (float)(rc[r] * cc[c]);
        float tm = (g_Stop[t] + (float)BB * pix * btsum) / (pix * (float)(BB * 36));
        float bm = (g_Sbot[t] + (float)BB * pix * bb0) / (pix * (float)BB);
        g_topm[t] = tm;
        float sg = 1.f / (1.f + expf(-bm));
        g_sig[t] = sg;
        #pragma unroll
        for (int b = 0; b < BB; b++)
            out[OUTX + b * NCELL + t] = sg;
    }
}

// ---------------------------------------------------------------------------
// Kernel 4: broadcast fill of channels 0..35 (top_m) and 54 (sigmoid(bot_m)).
// ---------------------------------------------------------------------------
__global__ __launch_bounds__(256) void bcast_kernel(
    const int* __restrict__ row_seg, const int* __restrict__ col_seg,
    float* __restrict__ out)
{
    unsigned i  = blockIdx.x * 256u + threadIdx.x;   // over B*H*W/4
    unsigned x4 = (i & 127u) << 2;
    unsigned y  = (i >> 7) & 511u;
    unsigned b  = i >> 16;
    int rb = __ldg(&row_seg[y]) * NCc;
    int c0 = __ldg(&col_seg[x4]);
    int c1 = __ldg(&col_seg[x4 + 1]);
    int c2 = __ldg(&col_seg[x4 + 2]);
    int c3 = __ldg(&col_seg[x4 + 3]);
    float4 tv = make_float4(g_topm[rb + c0], g_topm[rb + c1],
                            g_topm[rb + c2], g_topm[rb + c3]);
    float4 sv = make_float4(g_sig[rb + c0], g_sig[rb + c1],
                            g_sig[rb + c2], g_sig[rb + c3]);
    unsigned base = ((b * (unsigned)CINC) << 18) + (y << 9) + x4;
    #pragma unroll
    for (int ch = 0; ch < 36; ch++)
        *(float4*)&out[base + ((unsigned)ch << 18)] = tv;
    *(float4*)&out[base + (54u << 18)] = sv;
}

// ---------------------------------------------------------------------------
extern "C" void kernel_launch(void* const* d_in, const int* in_sizes, int n_in,
                              void* d_out, int out_size) {
    const float* x       = (const float*)d_in[0];
    const int*   row_seg = (const int*)d_in[1];
    const int*   col_seg = (const int*)d_in[2];
    const float* w1 = (const float*)d_in[3];
    const float* b1 = (const float*)d_in[4];
    const float* w2 = (const float*)d_in[5];
    const float* b2 = (const float*)d_in[6];
    const float* w3 = (const float*)d_in[7];
    const float* b3 = (const float*)d_in[8];
    const float* wt = (const float*)d_in[9];
    const float* bt = (const float*)d_in[10];
    const float* wb = (const float*)d_in[11];
    const float* bb = (const float*)d_in[12];
    float* out = (float*)d_out;

    prep_kernel<<<39, 640>>>(w1, w2, w3, wt);

    dim3 grid((WW + 47) / 48, HH / 32, BB * 3);   // 11 x 16 x 12
    conv_kernel<<<grid, 128>>>(x, row_seg, col_seg, b1, b2, b3, wb, out);

    finalize_kernel<<<1, 640>>>(row_seg, col_seg, bt, bb, out);

    bcast_kernel<<<(BB * HH * WW / 4) / 256, 256>>>(row_seg, col_seg, out);
}

// round 11
// speedup vs baseline: 2.5447x; 2.0951x over previous
#include <cuda_runtime.h>

#define HH   512
#define WW   512
#define BB   4
#define CINC 55
#define NRr  30
#define NCc  20
#define NCELL 600
#define OUTX 57671680   // 4*55*512*512

// Scratch (device globals; no allocation)
__device__ float g_Stop[NCELL];
__device__ float g_Sbot[NCELL];
__device__ float g_topm[NCELL];
__device__ float g_sig[NCELL];
__device__ float g_wtsum[18];
// Pre-arranged B fragments for mma.m16n8k8.tf32:
// [d][tap][chunk][lane*2 + {0,1}] = tf32(W[n=lane/4][ch=8*chunk+(lane%4)(+4)][tap])
__device__ float g_bfrag[3 * 25 * 7 * 64];

__device__ __forceinline__ unsigned f2tf32(float v) {
    unsigned r;
    asm("cvt.rna.tf32.f32 %0, %1;" : "=r"(r) : "f"(v));
    return r;
}

__device__ __forceinline__ void mma_tf32(float c[4],
                                         unsigned a0, unsigned a1,
                                         unsigned a2, unsigned a3,
                                         unsigned b0, unsigned b1) {
    asm volatile(
        "mma.sync.aligned.m16n8k8.row.col.f32.tf32.tf32.f32 "
        "{%0,%1,%2,%3}, {%4,%5,%6,%7}, {%8,%9}, {%0,%1,%2,%3};"
        : "+f"(c[0]), "+f"(c[1]), "+f"(c[2]), "+f"(c[3])
        : "r"(a0), "r"(a1), "r"(a2), "r"(a3), "r"(b0), "r"(b1));
}

// ---------------------------------------------------------------------------
// Kernel 1: zero cell accumulators; fold top head (36->18 channel-sum);
// build lane-ordered tf32 B-fragments for every (dilation, tap, chunk).
// ---------------------------------------------------------------------------
__global__ __launch_bounds__(256) void prep_kernel(
    const float* __restrict__ w1, const float* __restrict__ w2,
    const float* __restrict__ w3, const float* __restrict__ wt)
{
    int idx = blockIdx.x * 256 + threadIdx.x;
    if (idx < 16800) {                     // 3*25*7*32 lanes
        int lane = idx & 31;
        int t2   = idx >> 5;               // 0..524
        int kc   = t2 % 7;
        int t3   = t2 / 7;
        int kk   = t3 % 25;
        int d    = t3 / 25;
        const float* w = (d == 0) ? w1 : (d == 1 ? w2 : w3);
        int n   = lane >> 2;
        int klo = lane & 3;
        float v0 = 0.f, v1 = 0.f;
        if (n < 6) {
            int ch0 = kc * 8 + klo;
            int ch1 = ch0 + 4;
            if (ch0 < CINC) v0 = w[(n * CINC + ch0) * 25 + kk];
            if (ch1 < CINC) v1 = w[(n * CINC + ch1) * 25 + kk];
        }
        int base = ((d * 25 + kk) * 7 + kc) * 64 + lane * 2;
        g_bfrag[base]     = __uint_as_float(f2tf32(v0));
        g_bfrag[base + 1] = __uint_as_float(f2tf32(v1));
    } else if (idx < 16800 + NCELL) {
        int t = idx - 16800;
        g_Stop[t] = 0.f;
        g_Sbot[t] = 0.f;
    } else if (idx < 16800 + NCELL + 18) {
        int t = idx - 16800 - NCELL;
        float s = 0.f;
        #pragma unroll 4
        for (int c = 0; c < 36; c++) s += wt[c * 18 + t];
        g_wtsum[t] = s;
    }
}

// ---------------------------------------------------------------------------
// Kernel 2: TF32 tensor-core dilated conv (shift-GEMM). Per block: one
// (batch, dilation), 32x32 pixel tile. K-loop over 7 channel chunks (8 ch
// staged as tf32 planes in SMEM, plane stride 1944 words -> conflict-free
// quad access). Inner loop over 25 taps: B-frag via one __ldg float2,
// 8 m-tiles (16 pixels each) per warp -> mma.m16n8k8.
// ---------------------------------------------------------------------------
#define PLSTRIDE 1944

template <int D>
__device__ __forceinline__ void conv_body(
    const float* __restrict__ x,
    const float* __restrict__ bias6,
    float* __restrict__ out,
    unsigned* sm, int b, int gx0, int gy0)
{
    constexpr int PAD = 2 * D;
    constexpr int SW  = 32 + 4 * D;
    constexpr int SH  = 32 + 4 * D;
    constexpr int OCB = 36 + 6 * (D - 1);

    const int tid  = threadIdx.x;
    const int lane = tid & 31;
    const int w    = tid >> 5;     // warp 0..7 -> rows w*4..w*4+3

    const int thrbase = (lane & 3) * PLSTRIDE + (lane >> 2);
    int mtoff[8];
    #pragma unroll
    for (int mt = 0; mt < 8; mt++)
        mtoff[mt] = (w * 4 + (mt >> 1)) * SW + (mt & 1) * 16 + thrbase;

    float acc[8][4];
    #pragma unroll
    for (int mt = 0; mt < 8; mt++)
        #pragma unroll
        for (int j = 0; j < 4; j++) acc[mt][j] = 0.f;

    for (int kc = 0; kc < 7; kc++) {
        // stage 8 channel planes (tf32-converted, zero-padded halo)
        for (int i = tid; i < 8 * SH * SW; i += 256) {
            int p   = i / (SH * SW);
            int rem = i - p * (SH * SW);
            int r   = rem / SW;
            int cc  = rem - r * SW;
            int ch  = kc * 8 + p;
            int gy  = gy0 - PAD + r;
            int gx  = gx0 - PAD + cc;
            float v = 0.f;
            if (ch < CINC && (unsigned)gy < 512u && (unsigned)gx < 512u)
                v = x[(((size_t)(b * CINC + ch)) << 18) + (gy << 9) + gx];
            sm[p * PLSTRIDE + r * SW + cc] = f2tf32(v);
        }
        __syncthreads();

        #pragma unroll 5
        for (int kk = 0; kk < 25; kk++) {
            float2 bf = *(const float2*)&g_bfrag[
                (((D - 1) * 25 + kk) * 7 + kc) * 64 + lane * 2];
            unsigned b0 = __float_as_uint(bf.x);
            unsigned b1 = __float_as_uint(bf.y);
            const int tapoff = (kk / 5) * D * SW + (kk % 5) * D;
            #pragma unroll
            for (int mt = 0; mt < 8; mt++) {
                const unsigned* ap = sm + mtoff[mt] + tapoff;
                unsigned a0 = ap[0];
                unsigned a1 = ap[8];
                unsigned a2 = ap[4 * PLSTRIDE];
                unsigned a3 = ap[4 * PLSTRIDE + 8];
                mma_tf32(acc[mt], a0, a1, a2, a3, b0, b1);
            }
        }
        __syncthreads();
    }

    // epilogue: bias + relu, scalar feat stores (C-frag layout)
    const int n0 = (lane & 3) * 2;
    if (n0 < 6) {
        float bi0 = __ldg(&bias6[n0]);
        float bi1 = __ldg(&bias6[n0 + 1]);
        const size_t ch0base = ((size_t)(b * CINC + OCB + n0))     << 18;
        const size_t ch1base = ((size_t)(b * CINC + OCB + n0 + 1)) << 18;
        #pragma unroll
        for (int mt = 0; mt < 8; mt++) {
            int y  = gy0 + w * 4 + (mt >> 1);
            int gx = gx0 + (mt & 1) * 16 + (lane >> 2);
            unsigned pix = ((unsigned)y << 9) + (unsigned)gx;
            out[ch0base + pix]     = fmaxf(acc[mt][0] + bi0, 0.f);
            out[ch1base + pix]     = fmaxf(acc[mt][1] + bi1, 0.f);
            out[ch0base + pix + 8] = fmaxf(acc[mt][2] + bi0, 0.f);
            out[ch1base + pix + 8] = fmaxf(acc[mt][3] + bi1, 0.f);
        }
    }
}

extern __shared__ unsigned smu[];

__global__ __launch_bounds__(256, 2) void conv_kernel(
    const float* __restrict__ x,
    const float* __restrict__ b1, const float* __restrict__ b2,
    const float* __restrict__ b3,
    float* __restrict__ out)
{
    const int z   = blockIdx.z;
    const int b   = z / 3;
    const int d   = z - b * 3;
    const int gx0 = blockIdx.x * 32;
    const int gy0 = blockIdx.y * 32;
    if (d == 0)      conv_body<1>(x, b1, out, smu, b, gx0, gy0);
    else if (d == 1) conv_body<2>(x, b2, out, smu, b, gx0, gy0);
    else             conv_body<3>(x, b3, out, smu, b, gx0, gy0);
}

// ---------------------------------------------------------------------------
// Kernel 3: head reduction — read feat (channels 36..53) back (L2-hot),
// form per-pixel channel-sum head values, accumulate into per-cell sums.
// ---------------------------------------------------------------------------
__global__ __launch_bounds__(256) void reduce_kernel(
    const int* __restrict__ row_seg, const int* __restrict__ col_seg,
    const float* __restrict__ wbv, const float* __restrict__ out)
{
    __shared__ float cT[NCELL], cB[NCELL];
    __shared__ float swt[18], swb[18];
    const int tid = threadIdx.x;
    for (int t = tid; t < NCELL; t += 256) { cT[t] = 0.f; cB[t] = 0.f; }
    if (tid < 18) { swt[tid] = g_wtsum[tid]; swb[tid] = __ldg(&wbv[tid]); }
    __syncthreads();

    unsigned i  = blockIdx.x * 256u + tid;
    unsigned x4 = (i & 127u) << 2;
    unsigned y  = (i >> 7) & 511u;
    unsigned b  = i >> 16;
    float st0 = 0.f, st1 = 0.f, st2 = 0.f, st3 = 0.f;
    float sb0 = 0.f, sb1 = 0.f, sb2 = 0.f, sb3 = 0.f;
    const size_t base = ((size_t)(b * CINC + 36) << 18) + (y << 9) + x4;
    #pragma unroll
    for (int j = 0; j < 18; j++) {
        float4 f = *(const float4*)&out[base + ((size_t)j << 18)];
        float wj = swt[j], vj = swb[j];
        st0 = fmaf(wj, f.x, st0); st1 = fmaf(wj, f.y, st1);
        st2 = fmaf(wj, f.z, st2); st3 = fmaf(wj, f.w, st3);
        sb0 = fmaf(vj, f.x, sb0); sb1 = fmaf(vj, f.y, sb1);
        sb2 = fmaf(vj, f.z, sb2); sb3 = fmaf(vj, f.w, sb3);
    }
    const int rb = row_seg[y] * NCc;
    const int c0 = col_seg[x4],     c1 = col_seg[x4 + 1];
    const int c2 = col_seg[x4 + 2], c3 = col_seg[x4 + 3];
    atomicAdd(&cT[rb + c0], st0); atomicAdd(&cT[rb + c1], st1);
    atomicAdd(&cT[rb + c2], st2); atomicAdd(&cT[rb + c3], st3);
    atomicAdd(&cB[rb + c0], sb0); atomicAdd(&cB[rb + c1], sb1);
    atomicAdd(&cB[rb + c2], sb2); atomicAdd(&cB[rb + c3], sb3);
    __syncthreads();
    for (int t = tid; t < NCELL; t += 256) {
        float v0 = cT[t], v1 = cB[t];
        if (v0 != 0.f) atomicAdd(&g_Stop[t], v0);
        if (v1 != 0.f) atomicAdd(&g_Sbot[t], v1);
    }
}

// ---------------------------------------------------------------------------
// Kernel 4: finalize means (adding head biases) -> top_m, sigmoid(bot_m);
// write pools output.
// ---------------------------------------------------------------------------
__global__ __launch_bounds__(640) void finalize_kernel(
    const int* __restrict__ row_seg, const int* __restrict__ col_seg,
    const float* __restrict__ bt, const float* __restrict__ bb,
    float* __restrict__ out)
{
    __shared__ int rc[NRr];
    __shared__ int cc[NCc];
    int t = threadIdx.x;
    if (t < NRr) rc[t] = 0;
    if (t < NCc) cc[t] = 0;
    __syncthreads();
    if (t < 512) {
        atomicAdd(&rc[row_seg[t]], 1);
        atomicAdd(&cc[col_seg[t]], 1);
    }
    __syncthreads();
    if (t < NCELL) {
        float btsum = 0.f;
        for (int c = 0; c < 36; c++) btsum += bt[c];
        float bb0 = bb[0];
        int r = t / NCc, c = t - r * NCc;
        float pix = (float)(rc[r] * cc[c]);
        float tm = (g_Stop[t] + (float)BB * pix * btsum) / (pix * (float)(BB * 36));
        float bm = (g_Sbot[t] + (float)BB * pix * bb0) / (pix * (float)BB);
        g_topm[t] = tm;
        float sg = 1.f / (1.f + expf(-bm));
        g_sig[t] = sg;
        #pragma unroll
        for (int b = 0; b < BB; b++)
            out[OUTX + b * NCELL + t] = sg;
    }
}

// ---------------------------------------------------------------------------
// Kernel 5: broadcast fill of channels 0..35 (top_m) and 54 (sigmoid(bot_m)).
// ---------------------------------------------------------------------------
__global__ __launch_bounds__(256) void bcast_kernel(
    const int* __restrict__ row_seg, const int* __restrict__ col_seg,
    float* __restrict__ out)
{
    unsigned i  = blockIdx.x * 256u + threadIdx.x;   // over B*H*W/4
    unsigned x4 = (i & 127u) << 2;
    unsigned y  = (i >> 7) & 511u;
    unsigned b  = i >> 16;
    int rb = __ldg(&row_seg[y]) * NCc;
    int c0 = __ldg(&col_seg[x4]);
    int c1 = __ldg(&col_seg[x4 + 1]);
    int c2 = __ldg(&col_seg[x4 + 2]);
    int c3 = __ldg(&col_seg[x4 + 3]);
    float4 tv = make_float4(g_topm[rb + c0], g_topm[rb + c1],
                            g_topm[rb + c2], g_topm[rb + c3]);
    float4 sv = make_float4(g_sig[rb + c0], g_sig[rb + c1],
                            g_sig[rb + c2], g_sig[rb + c3]);
    unsigned base = ((b * (unsigned)CINC) << 18) + (y << 9) + x4;
    #pragma unroll
    for (int ch = 0; ch < 36; ch++)
        *(float4*)&out[base + ((unsigned)ch << 18)] = tv;
    *(float4*)&out[base + (54u << 18)] = sv;
}

// ---------------------------------------------------------------------------
extern "C" void kernel_launch(void* const* d_in, const int* in_sizes, int n_in,
                              void* d_out, int out_size) {
    const float* x       = (const float*)d_in[0];
    const int*   row_seg = (const int*)d_in[1];
    const int*   col_seg = (const int*)d_in[2];
    const float* w1 = (const float*)d_in[3];
    const float* b1 = (const float*)d_in[4];
    const float* w2 = (const float*)d_in[5];
    const float* b2 = (const float*)d_in[6];
    const float* w3 = (const float*)d_in[7];
    const float* b3 = (const float*)d_in[8];
    const float* wt = (const float*)d_in[9];
    const float* bt = (const float*)d_in[10];
    const float* wb = (const float*)d_in[11];
    const float* bb = (const float*)d_in[12];
    float* out = (float*)d_out;

    prep_kernel<<<69, 256>>>(w1, w2, w3, wt);

    const int smbytes = 8 * PLSTRIDE * 4;   // 62208
    cudaFuncSetAttribute(conv_kernel,
                         cudaFuncAttributeMaxDynamicSharedMemorySize, smbytes);
    dim3 grid(WW / 32, HH / 32, BB * 3);    // 16 x 16 x 12
    conv_kernel<<<grid, 256, smbytes>>>(x, b1, b2, b3, out);

    reduce_kernel<<<(BB * HH * WW / 4) / 256, 256>>>(row_seg, col_seg, wb, out);

    finalize_kernel<<<1, 640>>>(row_seg, col_seg, bt, bb, out);

    bcast_kernel<<<(BB * HH * WW / 4) / 256, 256>>>(row_seg, col_seg, out);
}